// round 5
// baseline (speedup 1.0000x reference)
#include <cuda_runtime.h>
#include <cuda_fp16.h>
#include <math.h>
#include <stdint.h>

// Problem constants: b=2, n=2048, d=256, e=16, h=8, dh=64, inner=512, nn=64
#define NROWS 4096

// ---- scratch (static device globals; no runtime allocation) ----
static __device__ float  g_qkv[NROWS * 1536];   // q|k|v per row (fp32)
static __device__ __half g_kvh[NROWS * 1024];   // k|v per row (fp16) for gathers
static __device__ float  g_att[NROWS * 512];    // attention feature output
static __device__ int    g_nb[NROWS * 64];      // neighbor indices

__device__ __forceinline__ float gelu_exact(float x){
    return 0.5f * x * (1.0f + erff(x * 0.7071067811865475f));
}

// ============================================================
// Double-buffered SGEMM: C[M,N] = A[M,K] @ B[K,N] (+bias)
// Tile BM x 64, K-slice 16, one __syncthreads per slice.
// ============================================================
template<int BM>
__global__ void __launch_bounds__(256) sgemm_db(
    const float* __restrict__ A, const float* __restrict__ B,
    const float* __restrict__ bias, float* __restrict__ C,
    int M, int N, int K)
{
    constexpr int R = BM / 16;              // rows per thread
    __shared__ float As[2][16][BM + 4];
    __shared__ float Bs[2][16][68];
    int t = threadIdx.x;
    int tx = t & 15, ty = t >> 4;
    int m0 = blockIdx.y * BM, n0 = blockIdx.x * 64;
    const float* Ab = A + (size_t)m0 * K;
    const float* Bb = B + n0;

    float acc[R][4];
#pragma unroll
    for (int ii = 0; ii < R; ii++)
#pragma unroll
        for (int jj = 0; jj < 4; jj++) acc[ii][jj] = 0.f;

    // loaders
    int brow = t >> 4, bcol = (t & 15) << 2;
    int arow, acol;
    if (BM == 64){ arow = t >> 2; acol = (t & 3) << 2; }
    else         { arow = t >> 3; acol = (t & 7) << 1; }

    float ra[4];
    float4 rbv;

    // prologue: tile 0
    if (BM == 64){
        float4 av = *(const float4*)(Ab + (size_t)arow * K + acol);
        ra[0]=av.x; ra[1]=av.y; ra[2]=av.z; ra[3]=av.w;
    } else {
        float2 av = *(const float2*)(Ab + (size_t)arow * K + acol);
        ra[0]=av.x; ra[1]=av.y;
    }
    rbv = *(const float4*)(Bb + (size_t)brow * N + bcol);
    {
        if (BM == 64){
            As[0][acol+0][arow]=ra[0]; As[0][acol+1][arow]=ra[1];
            As[0][acol+2][arow]=ra[2]; As[0][acol+3][arow]=ra[3];
        } else {
            As[0][acol+0][arow]=ra[0]; As[0][acol+1][arow]=ra[1];
        }
        *(float4*)&Bs[0][brow][bcol] = rbv;
    }
    __syncthreads();

    int T = K >> 4;
    int cur = 0;
    for (int tt = 0; tt < T; tt++){
        if (tt + 1 < T){
            int k0 = (tt + 1) << 4;
            if (BM == 64){
                float4 av = *(const float4*)(Ab + (size_t)arow * K + k0 + acol);
                ra[0]=av.x; ra[1]=av.y; ra[2]=av.z; ra[3]=av.w;
            } else {
                float2 av = *(const float2*)(Ab + (size_t)arow * K + k0 + acol);
                ra[0]=av.x; ra[1]=av.y;
            }
            rbv = *(const float4*)(Bb + (size_t)(k0 + brow) * N + bcol);
        }
#pragma unroll
        for (int kk = 0; kk < 16; kk++){
            float br[4];
            float4 b4 = *(const float4*)&Bs[cur][kk][tx << 2];
            br[0]=b4.x; br[1]=b4.y; br[2]=b4.z; br[3]=b4.w;
            float ar[R];
#pragma unroll
            for (int ii = 0; ii < R; ii++) ar[ii] = As[cur][kk][ty * R + ii];
#pragma unroll
            for (int ii = 0; ii < R; ii++)
#pragma unroll
                for (int jj = 0; jj < 4; jj++)
                    acc[ii][jj] = fmaf(ar[ii], br[jj], acc[ii][jj]);
        }
        if (tt + 1 < T){
            int nxt = cur ^ 1;
            if (BM == 64){
                As[nxt][acol+0][arow]=ra[0]; As[nxt][acol+1][arow]=ra[1];
                As[nxt][acol+2][arow]=ra[2]; As[nxt][acol+3][arow]=ra[3];
            } else {
                As[nxt][acol+0][arow]=ra[0]; As[nxt][acol+1][arow]=ra[1];
            }
            *(float4*)&Bs[nxt][brow][bcol] = rbv;
        }
        __syncthreads();
        cur ^= 1;
    }

#pragma unroll
    for (int ii = 0; ii < R; ii++){
        int m = m0 + ty * R + ii;
#pragma unroll
        for (int jj = 0; jj < 4; jj++){
            int nn = n0 + (tx << 2) + jj;
            float v = acc[ii][jj];
            if (bias) v += bias[nn];
            C[(size_t)m * N + nn] = v;
        }
    }
}

// ============================================================
// Pack k|v (cols 512..1535 of qkv) into fp16 for cheap gathers
// ============================================================
__global__ void __launch_bounds__(256) kv_half_kernel()
{
    int idx = blockIdx.x * 256 + threadIdx.x;     // 1M threads, 4 elems each
    int row = idx >> 8;
    int c4 = (idx & 255) << 2;
    float4 v = *(const float4*)&g_qkv[(size_t)row * 1536 + 512 + c4];
    __half2* p = (__half2*)&g_kvh[(size_t)row * 1024 + c4];
    p[0] = __floats2half2_rn(v.x, v.y);
    p[1] = __floats2half2_rn(v.z, v.w);
}

// ============================================================
// Top-64 nearest neighbors per row: 3-pass radix select on
// fp32 distance bit patterns (non-negative -> order-preserving)
// ============================================================
__global__ void __launch_bounds__(256) topk_kernel(const float* __restrict__ coors)
{
    __shared__ int hist[2048];
    __shared__ int wsum[8];
    __shared__ int sel_bin, sel_base;
    __shared__ int res_cnt, eq_cnt;
    __shared__ int res[64];
    __shared__ int eqlist[128];

    int tid = threadIdx.x;
    int row = blockIdx.x;
    int b = row >> 11, i = row & 2047;
    const float* cbp = coors + (size_t)b * 2048 * 3;
    float xi = cbp[i*3+0], yi = cbp[i*3+1], zi = cbp[i*3+2];

    unsigned u[8];
#pragma unroll
    for (int r = 0; r < 8; r++){
        int c = r * 256 + tid;
        float dx = xi - cbp[c*3+0];
        float dy = yi - cbp[c*3+1];
        float dz = zi - cbp[c*3+2];
        u[r] = __float_as_uint(sqrtf(dx*dx + dy*dy + dz*dz));
    }

    int k = 64;
    unsigned prefix = 0, pmask = 0;
#pragma unroll
    for (int p = 0; p < 3; p++){
        const int sh = (p == 0) ? 21 : (p == 1) ? 10 : 0;
        const int nbins = (p == 2) ? 1024 : 2048;
        const unsigned bm = (unsigned)nbins - 1u;
        for (int x = tid; x < nbins; x += 256) hist[x] = 0;
        __syncthreads();
#pragma unroll
        for (int r = 0; r < 8; r++)
            if ((u[r] & pmask) == prefix) atomicAdd(&hist[(u[r] >> sh) & bm], 1);
        __syncthreads();
        int per = nbins >> 8;
        int s = 0;
        for (int q = 0; q < per; q++) s += hist[tid * per + q];
        int lane = tid & 31, wid = tid >> 5;
        int x = s;
#pragma unroll
        for (int o = 1; o < 32; o <<= 1){
            int y = __shfl_up_sync(0xffffffffu, x, o);
            if (lane >= o) x += y;
        }
        if (lane == 31) wsum[wid] = x;
        __syncthreads();
        int add = 0;
#pragma unroll
        for (int q = 0; q < 8; q++) if (q < wid) add += wsum[q];
        int incl = x + add;
        int excl = incl - s;
        if (excl < k && k <= incl){
            int running = excl;
            for (int q = 0; q < per; q++){
                int c = hist[tid * per + q];
                if (running < k && k <= running + c){
                    sel_bin = tid * per + q;
                    sel_base = running;
                    break;
                }
                running += c;
            }
        }
        __syncthreads();
        k -= sel_base;
        prefix |= ((unsigned)sel_bin) << sh;
        pmask |= bm << sh;
        __syncthreads();
    }
    unsigned D = prefix;
    if (tid == 0){ res_cnt = 0; eq_cnt = 0; }
    __syncthreads();
#pragma unroll
    for (int r = 0; r < 8; r++){
        int c = r * 256 + tid;
        if (u[r] < D){
            int p = atomicAdd(&res_cnt, 1);
            res[p] = c;
        } else if (u[r] == D){
            int p = atomicAdd(&eq_cnt, 1);
            if (p < 128) eqlist[p] = c;
        }
    }
    __syncthreads();
    if (tid == 0){
        int ec = eq_cnt < 128 ? eq_cnt : 128;
        int base = res_cnt;
        for (int a = 0; a < k; a++){      // take k smallest indices among ties
            int best = 0x7fffffff, bi = -1;
            for (int q = 0; q < ec; q++)
                if (eqlist[q] < best){ best = eqlist[q]; bi = q; }
            res[base + a] = best;
            if (bi >= 0) eqlist[bi] = 0x7fffffff;
        }
    }
    __syncthreads();
    if (tid < 64) g_nb[row * 64 + tid] = res[tid];
}

// ============================================================
// Fused per-row attention kernel: one block per (b,i)
// ============================================================
__global__ void __launch_bounds__(256) main_kernel(
    const float* __restrict__ coors,
    const float* __restrict__ edges,
    const float* __restrict__ W_e1, const float* __restrict__ b_e1,
    const float* __restrict__ W_e2, const float* __restrict__ b_e2,
    const float* __restrict__ W_c,  const float* __restrict__ b_c,
    const float* __restrict__ W_g,  const float* __restrict__ b_g,
    const float* __restrict__ combine, const float* __restrict__ cscale,
    float* __restrict__ out_coors)
{
    __shared__ float q_s[512];
    __shared__ float cs_c[2048];
    __shared__ float cs_s[2048];
    __shared__ float qkraw[64][9];
    __shared__ float e_s[64][17];
    __shared__ float s_s[64][9];
    __shared__ float gs_s[64][9];
    __shared__ float attn_s[64][9];
    __shared__ float ws_s[64][9];
    __shared__ float gate_s[64][9];
    __shared__ float reln[64][4];
    __shared__ float t_s[64];
    __shared__ int   nb_s[64];
    __shared__ float we1[24*48];
    __shared__ float be1[48];
    __shared__ float we2[48*8];
    __shared__ float be2[8];
    __shared__ float wc[64], bc[8], wg[64], bg[8];
    __shared__ float delta_sm[3];

    int tid = threadIdx.x;
    int w = tid >> 5, l = tid & 31;
    int row = blockIdx.x;
    int b = row >> 11, i = row & 2047;
    const __half2* kvh = (const __half2*)g_kvh + (size_t)b * 2048 * 512;

    for (int x = tid; x < 1152; x += 256) we1[x] = W_e1[x];
    for (int x = tid; x < 384;  x += 256) we2[x] = W_e2[x];
    if (tid < 48) be1[tid] = b_e1[tid];
    if (tid < 8){ be2[tid] = b_e2[tid]; bc[tid] = b_c[tid]; bg[tid] = b_g[tid]; }
    if (tid < 64){ wc[tid] = W_c[tid]; wg[tid] = W_g[tid]; }
    if (tid < 3) delta_sm[tid] = 0.f;
    {
        const float* qrow = g_qkv + (size_t)row * 1536;
        for (int x = tid; x < 512; x += 256) q_s[x] = qrow[x];
    }
    if (tid < 64) nb_s[tid] = g_nb[row * 64 + tid];
    __syncthreads();

    float scl = cscale[0];
    if (tid < 64){
        int j = nb_s[tid];
        const float* cp = coors + (size_t)b * 2048 * 3;
        float dx = cp[i*3+0] - cp[j*3+0];
        float dy = cp[i*3+1] - cp[j*3+1];
        float dz = cp[i*3+2] - cp[j*3+2];
        float d = sqrtf(dx*dx + dy*dy + dz*dz);
        t_s[tid] = fminf(d * 100.f, 5000.f);
        float inv = scl / fmaxf(d, 1e-8f);
        reln[tid][0] = dx * inv;
        reln[tid][1] = dy * inv;
        reln[tid][2] = dz * inv;
    }
    __syncthreads();

    // rotary sin/cos table: 64 neighbors x 32 pairs, shared by k and v passes
    const float NEG_L2T_OVER32 = -0.41524101186092029f;  // -log2(10000)/32
    for (int x = tid; x < 2048; x += 256){
        int j = x >> 5, li = x & 31;
        float invf = exp2f((float)li * NEG_L2T_OVER32);
        float ang = t_s[j] * invf;
        // Cody-Waite 2-term 2*pi range reduction (angles up to 5000 rad)
        float nq = rintf(ang * 0.15915494309189535f);
        float r = fmaf(nq, -6.2831854820251465f, ang);
        r = fmaf(nq, 1.7484556e-7f, r);
        float sv, cv;
        __sincosf(r, &sv, &cv);
        cs_s[x] = sv; cs_c[x] = cv;
    }

    // gather edges: 4 threads per neighbor, float4 global -> scalar smem (pad 17)
    {
        int j = tid >> 2, q4 = (tid & 3) << 2;
        const float* ep = edges + (((size_t)(b * 2048 + i)) * 2048 + (size_t)nb_s[j]) * 16 + q4;
        float4 ev = *(const float4*)ep;
        e_s[j][q4+0] = ev.x; e_s[j][q4+1] = ev.y;
        e_s[j][q4+2] = ev.z; e_s[j][q4+3] = ev.w;
    }
    __syncthreads();

    // k-pass: warp w = head w; lane l owns rotary pair l (fp16 k gather)
    {
        float q0 = q_s[w*64 + 2*l], q1 = q_s[w*64 + 2*l + 1];
        for (int j = 0; j < 64; j++){
            __half2 kh = kvh[(size_t)nb_s[j] * 512 + w*32 + l];
            float2 kv = __half22float2(kh);
            float cv = cs_c[j*32 + l], sv = cs_s[j*32 + l];
            float kr0 = kv.x * cv - kv.y * sv;
            float kr1 = fmaf(kv.y, cv, kv.x * sv);
            float p = fmaf(q0, kr0, q1 * kr1);
#pragma unroll
            for (int o = 16; o > 0; o >>= 1) p += __shfl_xor_sync(0xffffffffu, p, o);
            if (l == 0) qkraw[j][w] = p;
        }
    }
    for (int x = tid; x < 512; x += 256) s_s[x >> 3][x & 7] = be2[x & 7];
    __syncthreads();

    // edge MLP 24 -> 48 (GELU) -> 8, fused: 4 threads/neighbor, 12 hidden each
    {
        int j = tid & 63, part = tid >> 6, hd0 = part * 12;
        float hid[12];
#pragma unroll
        for (int hh = 0; hh < 12; hh++){
            int hd = hd0 + hh;
            float z = be1[hd];
#pragma unroll
            for (int p = 0; p < 8; p++)  z = fmaf(qkraw[j][p], we1[p*48 + hd], z);
#pragma unroll
            for (int p = 0; p < 16; p++) z = fmaf(e_s[j][p], we1[(8+p)*48 + hd], z);
            hid[hh] = gelu_exact(z);
        }
#pragma unroll
        for (int h = 0; h < 8; h++){
            float acc = 0.f;
#pragma unroll
            for (int hh = 0; hh < 12; hh++)
                acc = fmaf(hid[hh], we2[(hd0+hh)*8 + h], acc);
            atomicAdd(&s_s[j][h], acc);
        }
    }
    __syncthreads();

    for (int x = tid; x < 512; x += 256){
        int jj = x >> 3, h = x & 7;
        gs_s[jj][h] = gelu_exact(s_s[jj][h]);
    }
    __syncthreads();
    for (int x = tid; x < 512; x += 256){
        int jj = x >> 3, h = x & 7;
        float cw = bc[h], gt = bg[h];
#pragma unroll
        for (int p = 0; p < 8; p++){
            cw = fmaf(gs_s[jj][p], wc[p*8 + h], cw);
            gt = fmaf(s_s[jj][p],  wg[p*8 + h], gt);
        }
        ws_s[jj][h] = cw;              // coor logits (pre-softmax)
        gate_s[jj][h] = tanhf(gt);
    }
    __syncthreads();

    // dual softmax over j per head (warp w); lanes cover j = l and l+32
    {
        float sa = s_s[l][w], sb = s_s[l+32][w];
        float m = fmaxf(sa, sb);
#pragma unroll
        for (int o = 16; o > 0; o >>= 1) m = fmaxf(m, __shfl_xor_sync(0xffffffffu, m, o));
        float ea = __expf(sa - m), eb = __expf(sb - m);
        float sum = ea + eb;
#pragma unroll
        for (int o = 16; o > 0; o >>= 1) sum += __shfl_xor_sync(0xffffffffu, sum, o);
        float inv = 1.f / sum;
        attn_s[l][w] = ea * inv;
        attn_s[l+32][w] = eb * inv;

        float ca = ws_s[l][w], cb2 = ws_s[l+32][w];
        float m2 = fmaxf(ca, cb2);
#pragma unroll
        for (int o = 16; o > 0; o >>= 1) m2 = fmaxf(m2, __shfl_xor_sync(0xffffffffu, m2, o));
        float e2a = __expf(ca - m2), e2b = __expf(cb2 - m2);
        float sum2 = e2a + e2b;
#pragma unroll
        for (int o = 16; o > 0; o >>= 1) sum2 += __shfl_xor_sync(0xffffffffu, sum2, o);
        float inv2 = 1.f / sum2;
        ws_s[l][w]    = e2a * inv2 * gate_s[l][w];
        ws_s[l+32][w] = e2b * inv2 * gate_s[l+32][w];
    }
    __syncthreads();

    // coordinate delta: warp w accumulates its head, combine across heads
    {
        float wa = ws_s[l][w], wb = ws_s[l+32][w];
        float d0 = wa * reln[l][0] + wb * reln[l+32][0];
        float d1 = wa * reln[l][1] + wb * reln[l+32][1];
        float d2 = wa * reln[l][2] + wb * reln[l+32][2];
#pragma unroll
        for (int o = 16; o > 0; o >>= 1){
            d0 += __shfl_xor_sync(0xffffffffu, d0, o);
            d1 += __shfl_xor_sync(0xffffffffu, d1, o);
            d2 += __shfl_xor_sync(0xffffffffu, d2, o);
        }
        if (l == 0){
            float cmb = combine[w];
            atomicAdd(&delta_sm[0], d0 * cmb);
            atomicAdd(&delta_sm[1], d1 * cmb);
            atomicAdd(&delta_sm[2], d2 * cmb);
        }
    }

    // v-pass: attn-weighted rotated v accumulation (fp16 v gather)
    {
        float a0 = 0.f, a1 = 0.f;
        for (int j = 0; j < 64; j++){
            float a = attn_s[j][w];
            __half2 vh = kvh[(size_t)nb_s[j] * 512 + 256 + w*32 + l];
            float2 vv = __half22float2(vh);
            float cv = cs_c[j*32 + l], sv = cs_s[j*32 + l];
            float vr0 = vv.x * cv - vv.y * sv;
            float vr1 = fmaf(vv.y, cv, vv.x * sv);
            a0 = fmaf(a, vr0, a0);
            a1 = fmaf(a, vr1, a1);
        }
        g_att[(size_t)row * 512 + w*64 + 2*l]     = a0;
        g_att[(size_t)row * 512 + w*64 + 2*l + 1] = a1;
    }
    __syncthreads();
    if (tid < 3) out_coors[row * 3 + tid] = delta_sm[tid];
}

// ============================================================
extern "C" void kernel_launch(void* const* d_in, const int* in_sizes, int n_in,
                              void* d_out, int out_size)
{
    const float* feats   = (const float*)d_in[0];
    const float* coors   = (const float*)d_in[1];
    const float* edges   = (const float*)d_in[2];
    const float* W_qkv   = (const float*)d_in[3];
    const float* W_out   = (const float*)d_in[4];
    const float* b_out   = (const float*)d_in[5];
    const float* W_e1    = (const float*)d_in[6];
    const float* b_e1    = (const float*)d_in[7];
    const float* W_e2    = (const float*)d_in[8];
    const float* b_e2    = (const float*)d_in[9];
    const float* W_c     = (const float*)d_in[10];
    const float* b_c     = (const float*)d_in[11];
    const float* W_g     = (const float*)d_in[12];
    const float* b_g     = (const float*)d_in[13];
    const float* combine = (const float*)d_in[14];
    const float* cscale  = (const float*)d_in[15];
    float* out = (float*)d_out;

    void *p_qkv = 0, *p_att = 0;
    cudaGetSymbolAddress(&p_qkv, g_qkv);
    cudaGetSymbolAddress(&p_att, g_att);

    // 1) QKV projection: (4096,256) @ (256,1536)
    sgemm_db<64><<<dim3(1536/64, 4096/64), 256>>>(
        feats, W_qkv, nullptr, (float*)p_qkv, 4096, 1536, 256);

    // 1b) pack k|v to fp16 for the gather-heavy kernel
    kv_half_kernel<<<4096, 256>>>();

    // 2) top-64 neighbors per row
    topk_kernel<<<4096, 256>>>(coors);

    // 3) fused attention; writes g_att and coors_delta region of d_out
    main_kernel<<<4096, 256>>>(coors, edges,
        W_e1, b_e1, W_e2, b_e2, W_c, b_c, W_g, b_g,
        combine, cscale, out + 2*2048*256);

    // 4) output projection: (4096,512) @ (512,256) + b_out -> node_out
    sgemm_db<32><<<dim3(256/64, 4096/32), 256>>>(
        (const float*)p_att, W_out, b_out, out, 4096, 256, 512);
}

// round 6
// speedup vs baseline: 1.3002x; 1.3002x over previous
#include <cuda_runtime.h>
#include <cuda_fp16.h>
#include <math.h>
#include <stdint.h>

// Problem constants: b=2, n=2048, d=256, e=16, h=8, dh=64, inner=512, nn=64
#define NROWS 4096

// ---- scratch (static device globals; no runtime allocation) ----
static __device__ float  g_qkv[NROWS * 1536];   // q|k|v per row (fp32)
static __device__ __half g_kvh[NROWS * 1024];   // k|v per row (fp16) for gathers
static __device__ float  g_att[NROWS * 512];    // attention feature output
static __device__ int    g_nb[NROWS * 64];      // neighbor indices

__device__ __forceinline__ float gelu_exact(float x){
    return 0.5f * x * (1.0f + erff(x * 0.7071067811865475f));
}

// ============================================================
// Double-buffered SGEMM: C[M,N] = A[M,K] @ B[K,N] (+bias)
// Tile BM x 64, K-slice 16, one __syncthreads per slice.
// Optional fp16 epilogue copy for columns >= 512 (k|v pack).
// ============================================================
template<int BM>
__global__ void __launch_bounds__(256) sgemm_db(
    const float* __restrict__ A, const float* __restrict__ B,
    const float* __restrict__ bias, float* __restrict__ C,
    __half* __restrict__ KVH,
    int M, int N, int K)
{
    constexpr int R = BM / 16;              // rows per thread
    __shared__ float As[2][16][BM + 4];
    __shared__ float Bs[2][16][68];
    int t = threadIdx.x;
    int tx = t & 15, ty = t >> 4;
    int m0 = blockIdx.y * BM, n0 = blockIdx.x * 64;
    const float* Ab = A + (size_t)m0 * K;
    const float* Bb = B + n0;

    float acc[R][4];
#pragma unroll
    for (int ii = 0; ii < R; ii++)
#pragma unroll
        for (int jj = 0; jj < 4; jj++) acc[ii][jj] = 0.f;

    int brow = t >> 4, bcol = (t & 15) << 2;
    int arow, acol;
    if (BM == 64){ arow = t >> 2; acol = (t & 3) << 2; }
    else         { arow = t >> 3; acol = (t & 7) << 1; }

    float ra[4];
    float4 rbv;

    if (BM == 64){
        float4 av = *(const float4*)(Ab + (size_t)arow * K + acol);
        ra[0]=av.x; ra[1]=av.y; ra[2]=av.z; ra[3]=av.w;
    } else {
        float2 av = *(const float2*)(Ab + (size_t)arow * K + acol);
        ra[0]=av.x; ra[1]=av.y;
    }
    rbv = *(const float4*)(Bb + (size_t)brow * N + bcol);
    {
        if (BM == 64){
            As[0][acol+0][arow]=ra[0]; As[0][acol+1][arow]=ra[1];
            As[0][acol+2][arow]=ra[2]; As[0][acol+3][arow]=ra[3];
        } else {
            As[0][acol+0][arow]=ra[0]; As[0][acol+1][arow]=ra[1];
        }
        *(float4*)&Bs[0][brow][bcol] = rbv;
    }
    __syncthreads();

    int T = K >> 4;
    int cur = 0;
    for (int tt = 0; tt < T; tt++){
        if (tt + 1 < T){
            int k0 = (tt + 1) << 4;
            if (BM == 64){
                float4 av = *(const float4*)(Ab + (size_t)arow * K + k0 + acol);
                ra[0]=av.x; ra[1]=av.y; ra[2]=av.z; ra[3]=av.w;
            } else {
                float2 av = *(const float2*)(Ab + (size_t)arow * K + k0 + acol);
                ra[0]=av.x; ra[1]=av.y;
            }
            rbv = *(const float4*)(Bb + (size_t)(k0 + brow) * N + bcol);
        }
#pragma unroll
        for (int kk = 0; kk < 16; kk++){
            float br[4];
            float4 b4 = *(const float4*)&Bs[cur][kk][tx << 2];
            br[0]=b4.x; br[1]=b4.y; br[2]=b4.z; br[3]=b4.w;
            float ar[R];
#pragma unroll
            for (int ii = 0; ii < R; ii++) ar[ii] = As[cur][kk][ty * R + ii];
#pragma unroll
            for (int ii = 0; ii < R; ii++)
#pragma unroll
                for (int jj = 0; jj < 4; jj++)
                    acc[ii][jj] = fmaf(ar[ii], br[jj], acc[ii][jj]);
        }
        if (tt + 1 < T){
            int nxt = cur ^ 1;
            if (BM == 64){
                As[nxt][acol+0][arow]=ra[0]; As[nxt][acol+1][arow]=ra[1];
                As[nxt][acol+2][arow]=ra[2]; As[nxt][acol+3][arow]=ra[3];
            } else {
                As[nxt][acol+0][arow]=ra[0]; As[nxt][acol+1][arow]=ra[1];
            }
            *(float4*)&Bs[nxt][brow][bcol] = rbv;
        }
        __syncthreads();
        cur ^= 1;
    }

    bool dokv = (KVH != nullptr) && (n0 >= 512);
#pragma unroll
    for (int ii = 0; ii < R; ii++){
        int m = m0 + ty * R + ii;
        int nn = n0 + (tx << 2);
        float v0 = acc[ii][0], v1 = acc[ii][1], v2 = acc[ii][2], v3 = acc[ii][3];
        if (bias){ v0 += bias[nn]; v1 += bias[nn+1]; v2 += bias[nn+2]; v3 += bias[nn+3]; }
        float4 ov = make_float4(v0, v1, v2, v3);
        *(float4*)&C[(size_t)m * N + nn] = ov;
        if (dokv){
            __half2 h0 = __floats2half2_rn(v0, v1);
            __half2 h1 = __floats2half2_rn(v2, v3);
            __half2* hp = (__half2*)(KVH + (size_t)m * 1024 + (nn - 512));
            hp[0] = h0; hp[1] = h1;
        }
    }
}

// ============================================================
// Top-64 nearest neighbors per row: 3-pass radix select on
// fp32 distance bit patterns (non-negative -> order-preserving)
// ============================================================
__global__ void __launch_bounds__(256) topk_kernel(const float* __restrict__ coors)
{
    __shared__ int hist[2048];
    __shared__ int wsum[8];
    __shared__ int sel_bin, sel_base;
    __shared__ int res_cnt, eq_cnt;
    __shared__ int res[64];
    __shared__ int eqlist[128];

    int tid = threadIdx.x;
    int row = blockIdx.x;
    int b = row >> 11, i = row & 2047;
    const float* cbp = coors + (size_t)b * 2048 * 3;
    float xi = cbp[i*3+0], yi = cbp[i*3+1], zi = cbp[i*3+2];

    unsigned u[8];
#pragma unroll
    for (int r = 0; r < 8; r++){
        int c = r * 256 + tid;
        float dx = xi - cbp[c*3+0];
        float dy = yi - cbp[c*3+1];
        float dz = zi - cbp[c*3+2];
        u[r] = __float_as_uint(sqrtf(dx*dx + dy*dy + dz*dz));
    }

    int k = 64;
    unsigned prefix = 0, pmask = 0;
#pragma unroll
    for (int p = 0; p < 3; p++){
        const int sh = (p == 0) ? 21 : (p == 1) ? 10 : 0;
        const int nbins = (p == 2) ? 1024 : 2048;
        const unsigned bm = (unsigned)nbins - 1u;
        for (int x = tid; x < nbins; x += 256) hist[x] = 0;
        __syncthreads();
#pragma unroll
        for (int r = 0; r < 8; r++)
            if ((u[r] & pmask) == prefix) atomicAdd(&hist[(u[r] >> sh) & bm], 1);
        __syncthreads();
        int per = nbins >> 8;
        int s = 0;
        for (int q = 0; q < per; q++) s += hist[tid * per + q];
        int lane = tid & 31, wid = tid >> 5;
        int x = s;
#pragma unroll
        for (int o = 1; o < 32; o <<= 1){
            int y = __shfl_up_sync(0xffffffffu, x, o);
            if (lane >= o) x += y;
        }
        if (lane == 31) wsum[wid] = x;
        __syncthreads();
        int add = 0;
#pragma unroll
        for (int q = 0; q < 8; q++) if (q < wid) add += wsum[q];
        int incl = x + add;
        int excl = incl - s;
        if (excl < k && k <= incl){
            int running = excl;
            for (int q = 0; q < per; q++){
                int c = hist[tid * per + q];
                if (running < k && k <= running + c){
                    sel_bin = tid * per + q;
                    sel_base = running;
                    break;
                }
                running += c;
            }
        }
        __syncthreads();
        k -= sel_base;
        prefix |= ((unsigned)sel_bin) << sh;
        pmask |= bm << sh;
        __syncthreads();
    }
    unsigned D = prefix;
    if (tid == 0){ res_cnt = 0; eq_cnt = 0; }
    __syncthreads();
#pragma unroll
    for (int r = 0; r < 8; r++){
        int c = r * 256 + tid;
        if (u[r] < D){
            int p = atomicAdd(&res_cnt, 1);
            res[p] = c;
        } else if (u[r] == D){
            int p = atomicAdd(&eq_cnt, 1);
            if (p < 128) eqlist[p] = c;
        }
    }
    __syncthreads();
    if (tid == 0){
        int ec = eq_cnt < 128 ? eq_cnt : 128;
        int base = res_cnt;
        for (int a = 0; a < k; a++){      // take k smallest indices among ties
            int best = 0x7fffffff, bi = -1;
            for (int q = 0; q < ec; q++)
                if (eqlist[q] < best){ best = eqlist[q]; bi = q; }
            res[base + a] = best;
            if (bi >= 0) eqlist[bi] = 0x7fffffff;
        }
    }
    __syncthreads();
    if (tid < 64) g_nb[row * 64 + tid] = res[tid];
}

// ============================================================
// Fused per-row attention kernel: one block per (b,i)
// k/v passes: lane = (jg in 0..3, dq in 0..7); one LDG.128 per
// lane covers 8 fp16 dims of one neighbor row; 16 iterations.
// ============================================================
__global__ void __launch_bounds__(256) main_kernel(
    const float* __restrict__ coors,
    const float* __restrict__ edges,
    const float* __restrict__ W_e1, const float* __restrict__ b_e1,
    const float* __restrict__ W_e2, const float* __restrict__ b_e2,
    const float* __restrict__ W_c,  const float* __restrict__ b_c,
    const float* __restrict__ W_g,  const float* __restrict__ b_g,
    const float* __restrict__ combine, const float* __restrict__ cscale,
    float* __restrict__ out_coors)
{
    __shared__ float q_s[512];
    __shared__ float cs_c[2048];
    __shared__ float cs_s[2048];
    __shared__ float qkraw[64][9];
    __shared__ float e_s[64][17];
    __shared__ float s_s[64][9];
    __shared__ float gs_s[64][9];
    __shared__ float attn_s[64][9];
    __shared__ float ws_s[64][9];
    __shared__ float gate_s[64][9];
    __shared__ float reln[64][4];
    __shared__ float t_s[64];
    __shared__ int   nb_s[64];
    __shared__ float we1[24*48];
    __shared__ float be1[48];
    __shared__ float we2[48*8];
    __shared__ float be2[8];
    __shared__ float wc[64], bc[8], wg[64], bg[8];
    __shared__ float delta_sm[3];

    int tid = threadIdx.x;
    int w = tid >> 5, l = tid & 31;
    int dq = l & 7, jg = l >> 3;
    int row = blockIdx.x;
    int b = row >> 11, i = row & 2047;
    const __half* kvb = g_kvh + (size_t)b * 2048 * 1024;

    for (int x = tid; x < 1152; x += 256) we1[x] = W_e1[x];
    for (int x = tid; x < 384;  x += 256) we2[x] = W_e2[x];
    if (tid < 48) be1[tid] = b_e1[tid];
    if (tid < 8){ be2[tid] = b_e2[tid]; bc[tid] = b_c[tid]; bg[tid] = b_g[tid]; }
    if (tid < 64){ wc[tid] = W_c[tid]; wg[tid] = W_g[tid]; }
    if (tid < 3) delta_sm[tid] = 0.f;
    {
        const float* qrow = g_qkv + (size_t)row * 1536;
        for (int x = tid; x < 512; x += 256) q_s[x] = qrow[x];
    }
    if (tid < 64) nb_s[tid] = g_nb[row * 64 + tid];
    __syncthreads();

    float scl = cscale[0];
    if (tid < 64){
        int j = nb_s[tid];
        const float* cp = coors + (size_t)b * 2048 * 3;
        float dx = cp[i*3+0] - cp[j*3+0];
        float dy = cp[i*3+1] - cp[j*3+1];
        float dz = cp[i*3+2] - cp[j*3+2];
        float d = sqrtf(dx*dx + dy*dy + dz*dz);
        t_s[tid] = fminf(d * 100.f, 5000.f);
        float inv = scl / fmaxf(d, 1e-8f);
        reln[tid][0] = dx * inv;
        reln[tid][1] = dy * inv;
        reln[tid][2] = dz * inv;
    }
    __syncthreads();

    // rotary sin/cos table: 64 neighbors x 32 pairs, shared by k and v passes
    const float NEG_L2T_OVER32 = -0.41524101186092029f;  // -log2(10000)/32
    for (int x = tid; x < 2048; x += 256){
        int j = x >> 5, li = x & 31;
        float invf = exp2f((float)li * NEG_L2T_OVER32);
        float ang = t_s[j] * invf;
        // Cody-Waite 2-term 2*pi range reduction (angles up to 5000 rad)
        float nq = rintf(ang * 0.15915494309189535f);
        float r = fmaf(nq, -6.2831854820251465f, ang);
        r = fmaf(nq, 1.7484556e-7f, r);
        float sv, cv;
        __sincosf(r, &sv, &cv);
        cs_s[x] = sv; cs_c[x] = cv;
    }

    // gather edges: 4 threads per neighbor, float4 global -> scalar smem (pad 17)
    {
        int j = tid >> 2, q4 = (tid & 3) << 2;
        const float* ep = edges + (((size_t)(b * 2048 + i)) * 2048 + (size_t)nb_s[j]) * 16 + q4;
        float4 ev = *(const float4*)ep;
        e_s[j][q4+0] = ev.x; e_s[j][q4+1] = ev.y;
        e_s[j][q4+2] = ev.z; e_s[j][q4+3] = ev.w;
    }
    __syncthreads();

    // k-pass: warp w = head w; lane (jg,dq): j = 4t+jg, dims dq*8..dq*8+7
    {
        float qreg[8];
#pragma unroll
        for (int x = 0; x < 8; x++) qreg[x] = q_s[w*64 + dq*8 + x];
#pragma unroll 4
        for (int t = 0; t < 16; t++){
            int j = t*4 + jg;
            const __half* kp = kvb + (size_t)nb_s[j] * 1024 + w*64 + dq*8;
            float4 kraw = *(const float4*)kp;
            const __half2* kh = (const __half2*)&kraw;
            float4 cc = *(const float4*)&cs_c[j*32 + dq*4];
            float4 ss = *(const float4*)&cs_s[j*32 + dq*4];
            float p = 0.f;
            {
                float2 kv = __half22float2(kh[0]);
                float kr0 = kv.x*cc.x - kv.y*ss.x, kr1 = fmaf(kv.y, cc.x, kv.x*ss.x);
                p = fmaf(qreg[0], kr0, p); p = fmaf(qreg[1], kr1, p);
            }{
                float2 kv = __half22float2(kh[1]);
                float kr0 = kv.x*cc.y - kv.y*ss.y, kr1 = fmaf(kv.y, cc.y, kv.x*ss.y);
                p = fmaf(qreg[2], kr0, p); p = fmaf(qreg[3], kr1, p);
            }{
                float2 kv = __half22float2(kh[2]);
                float kr0 = kv.x*cc.z - kv.y*ss.z, kr1 = fmaf(kv.y, cc.z, kv.x*ss.z);
                p = fmaf(qreg[4], kr0, p); p = fmaf(qreg[5], kr1, p);
            }{
                float2 kv = __half22float2(kh[3]);
                float kr0 = kv.x*cc.w - kv.y*ss.w, kr1 = fmaf(kv.y, cc.w, kv.x*ss.w);
                p = fmaf(qreg[6], kr0, p); p = fmaf(qreg[7], kr1, p);
            }
            p += __shfl_xor_sync(0xffffffffu, p, 1);
            p += __shfl_xor_sync(0xffffffffu, p, 2);
            p += __shfl_xor_sync(0xffffffffu, p, 4);
            if (dq == 0) qkraw[j][w] = p;
        }
    }
    for (int x = tid; x < 512; x += 256) s_s[x >> 3][x & 7] = be2[x & 7];
    __syncthreads();

    // edge MLP 24 -> 48 (GELU) -> 8, fused: 4 threads/neighbor, 12 hidden each
    {
        int j = tid & 63, part = tid >> 6, hd0 = part * 12;
        float hid[12];
#pragma unroll
        for (int hh = 0; hh < 12; hh++){
            int hd = hd0 + hh;
            float z = be1[hd];
#pragma unroll
            for (int p = 0; p < 8; p++)  z = fmaf(qkraw[j][p], we1[p*48 + hd], z);
#pragma unroll
            for (int p = 0; p < 16; p++) z = fmaf(e_s[j][p], we1[(8+p)*48 + hd], z);
            hid[hh] = gelu_exact(z);
        }
#pragma unroll
        for (int h = 0; h < 8; h++){
            float acc = 0.f;
#pragma unroll
            for (int hh = 0; hh < 12; hh++)
                acc = fmaf(hid[hh], we2[(hd0+hh)*8 + h], acc);
            atomicAdd(&s_s[j][h], acc);
        }
    }
    __syncthreads();

    for (int x = tid; x < 512; x += 256){
        int jj = x >> 3, h = x & 7;
        gs_s[jj][h] = gelu_exact(s_s[jj][h]);
    }
    __syncthreads();
    for (int x = tid; x < 512; x += 256){
        int jj = x >> 3, h = x & 7;
        float cw = bc[h], gt = bg[h];
#pragma unroll
        for (int p = 0; p < 8; p++){
            cw = fmaf(gs_s[jj][p], wc[p*8 + h], cw);
            gt = fmaf(s_s[jj][p],  wg[p*8 + h], gt);
        }
        ws_s[jj][h] = cw;              // coor logits (pre-softmax)
        gate_s[jj][h] = tanhf(gt);
    }
    __syncthreads();

    // dual softmax over j per head (warp w); lanes cover j = l and l+32
    {
        float sa = s_s[l][w], sb = s_s[l+32][w];
        float m = fmaxf(sa, sb);
#pragma unroll
        for (int o = 16; o > 0; o >>= 1) m = fmaxf(m, __shfl_xor_sync(0xffffffffu, m, o));
        float ea = __expf(sa - m), eb = __expf(sb - m);
        float sum = ea + eb;
#pragma unroll
        for (int o = 16; o > 0; o >>= 1) sum += __shfl_xor_sync(0xffffffffu, sum, o);
        float inv = 1.f / sum;
        attn_s[l][w] = ea * inv;
        attn_s[l+32][w] = eb * inv;

        float ca = ws_s[l][w], cb2 = ws_s[l+32][w];
        float m2 = fmaxf(ca, cb2);
#pragma unroll
        for (int o = 16; o > 0; o >>= 1) m2 = fmaxf(m2, __shfl_xor_sync(0xffffffffu, m2, o));
        float e2a = __expf(ca - m2), e2b = __expf(cb2 - m2);
        float sum2 = e2a + e2b;
#pragma unroll
        for (int o = 16; o > 0; o >>= 1) sum2 += __shfl_xor_sync(0xffffffffu, sum2, o);
        float inv2 = 1.f / sum2;
        ws_s[l][w]    = e2a * inv2 * gate_s[l][w];
        ws_s[l+32][w] = e2b * inv2 * gate_s[l+32][w];
    }
    __syncthreads();

    // coordinate delta: warp w accumulates its head, combine across heads
    {
        float wa = ws_s[l][w], wb = ws_s[l+32][w];
        float d0 = wa * reln[l][0] + wb * reln[l+32][0];
        float d1 = wa * reln[l][1] + wb * reln[l+32][1];
        float d2 = wa * reln[l][2] + wb * reln[l+32][2];
#pragma unroll
        for (int o = 16; o > 0; o >>= 1){
            d0 += __shfl_xor_sync(0xffffffffu, d0, o);
            d1 += __shfl_xor_sync(0xffffffffu, d1, o);
            d2 += __shfl_xor_sync(0xffffffffu, d2, o);
        }
        if (l == 0){
            float cmb = combine[w];
            atomicAdd(&delta_sm[0], d0 * cmb);
            atomicAdd(&delta_sm[1], d1 * cmb);
            atomicAdd(&delta_sm[2], d2 * cmb);
        }
    }

    // v-pass: attn-weighted rotated v accumulation, same lane tiling
    {
        float acc[8];
#pragma unroll
        for (int x = 0; x < 8; x++) acc[x] = 0.f;
#pragma unroll 4
        for (int t = 0; t < 16; t++){
            int j = t*4 + jg;
            float a = attn_s[j][w];
            const __half* vp = kvb + (size_t)nb_s[j] * 1024 + 512 + w*64 + dq*8;
            float4 vraw = *(const float4*)vp;
            const __half2* vh = (const __half2*)&vraw;
            float4 cc = *(const float4*)&cs_c[j*32 + dq*4];
            float4 ss = *(const float4*)&cs_s[j*32 + dq*4];
            {
                float2 vv = __half22float2(vh[0]);
                acc[0] = fmaf(a, vv.x*cc.x - vv.y*ss.x, acc[0]);
                acc[1] = fmaf(a, fmaf(vv.y, cc.x, vv.x*ss.x), acc[1]);
            }{
                float2 vv = __half22float2(vh[1]);
                acc[2] = fmaf(a, vv.x*cc.y - vv.y*ss.y, acc[2]);
                acc[3] = fmaf(a, fmaf(vv.y, cc.y, vv.x*ss.y), acc[3]);
            }{
                float2 vv = __half22float2(vh[2]);
                acc[4] = fmaf(a, vv.x*cc.z - vv.y*ss.z, acc[4]);
                acc[5] = fmaf(a, fmaf(vv.y, cc.z, vv.x*ss.z), acc[5]);
            }{
                float2 vv = __half22float2(vh[3]);
                acc[6] = fmaf(a, vv.x*cc.w - vv.y*ss.w, acc[6]);
                acc[7] = fmaf(a, fmaf(vv.y, cc.w, vv.x*ss.w), acc[7]);
            }
        }
#pragma unroll
        for (int x = 0; x < 8; x++){
            acc[x] += __shfl_xor_sync(0xffffffffu, acc[x], 8);
            acc[x] += __shfl_xor_sync(0xffffffffu, acc[x], 16);
        }
        if (jg == 0){
            float4* po = (float4*)&g_att[(size_t)row * 512 + w*64 + dq*8];
            po[0] = make_float4(acc[0], acc[1], acc[2], acc[3]);
            po[1] = make_float4(acc[4], acc[5], acc[6], acc[7]);
        }
    }
    __syncthreads();
    if (tid < 3) out_coors[row * 3 + tid] = delta_sm[tid];
}

// ============================================================
extern "C" void kernel_launch(void* const* d_in, const int* in_sizes, int n_in,
                              void* d_out, int out_size)
{
    const float* feats   = (const float*)d_in[0];
    const float* coors   = (const float*)d_in[1];
    const float* edges   = (const float*)d_in[2];
    const float* W_qkv   = (const float*)d_in[3];
    const float* W_out   = (const float*)d_in[4];
    const float* b_out   = (const float*)d_in[5];
    const float* W_e1    = (const float*)d_in[6];
    const float* b_e1    = (const float*)d_in[7];
    const float* W_e2    = (const float*)d_in[8];
    const float* b_e2    = (const float*)d_in[9];
    const float* W_c     = (const float*)d_in[10];
    const float* b_c     = (const float*)d_in[11];
    const float* W_g     = (const float*)d_in[12];
    const float* b_g     = (const float*)d_in[13];
    const float* combine = (const float*)d_in[14];
    const float* cscale  = (const float*)d_in[15];
    float* out = (float*)d_out;

    void *p_qkv = 0, *p_att = 0, *p_kvh = 0;
    cudaGetSymbolAddress(&p_qkv, g_qkv);
    cudaGetSymbolAddress(&p_att, g_att);
    cudaGetSymbolAddress(&p_kvh, g_kvh);

    // 1) QKV projection: (4096,256) @ (256,1536); epilogue also packs fp16 k|v
    sgemm_db<64><<<dim3(1536/64, 4096/64), 256>>>(
        feats, W_qkv, nullptr, (float*)p_qkv, (__half*)p_kvh, 4096, 1536, 256);

    // 2) top-64 neighbors per row
    topk_kernel<<<4096, 256>>>(coors);

    // 3) fused attention; writes g_att and coors_delta region of d_out
    main_kernel<<<4096, 256>>>(coors, edges,
        W_e1, b_e1, W_e2, b_e2, W_c, b_c, W_g, b_g,
        combine, cscale, out + 2*2048*256);

    // 4) output projection: (4096,512) @ (512,256) + b_out -> node_out
    sgemm_db<32><<<dim3(256/64, 4096/32), 256>>>(
        (const float*)p_att, W_out, b_out, out, nullptr, 4096, 256, 512);
}

// round 7
// speedup vs baseline: 1.3491x; 1.0376x over previous
#include <cuda_runtime.h>
#include <cuda_fp16.h>
#include <math.h>
#include <stdint.h>

// Problem constants: b=2, n=2048, d=256, e=16, h=8, dh=64, inner=512, nn=64
#define NROWS 4096

// ---- scratch (static device globals; no runtime allocation) ----
static __device__ float  g_qkv[NROWS * 1536];   // q|k|v per row (fp32); reused as split-K partials later
static __device__ __half g_kvh[NROWS * 1024];   // k|v per row (fp16) for gathers
static __device__ float  g_att[NROWS * 512];    // attention feature output
static __device__ int    g_nb[NROWS * 64];      // neighbor indices

__device__ __forceinline__ float gelu_exact(float x){
    return 0.5f * x * (1.0f + erff(x * 0.7071067811865475f));
}

// ============================================================
// Double-buffered SGEMM, 64x64 tile, 4x4/thread, float4 LDS.
// Supports split-K via gridDim.z: z-slice handles K cols
// [z*K, (z+1)*K) of A (row stride lda); partials (no bias) go
// to C + z*M*N when gridDim.z > 1.
// ============================================================
__global__ void __launch_bounds__(256) sgemm_db(
    const float* __restrict__ A, const float* __restrict__ B,
    const float* __restrict__ bias, float* __restrict__ C,
    __half* __restrict__ KVH,
    int M, int N, int K, int lda)
{
    __shared__ float As[2][16][68];
    __shared__ float Bs[2][16][68];
    int t = threadIdx.x;
    int tx = t & 15, ty = t >> 4;
    int m0 = blockIdx.y * 64, n0 = blockIdx.x * 64;
    int z = blockIdx.z;
    const float* Ab = A + (size_t)m0 * lda + (size_t)z * K;
    const float* Bb = B + (size_t)z * K * N + n0;
    float* Cb = (gridDim.z > 1) ? (C + (size_t)z * M * N) : C;
    const float* bz = (gridDim.z > 1) ? nullptr : bias;

    float acc[4][4];
#pragma unroll
    for (int ii = 0; ii < 4; ii++)
#pragma unroll
        for (int jj = 0; jj < 4; jj++) acc[ii][jj] = 0.f;

    int arow = t >> 2, acol = (t & 3) << 2;
    int brow = t >> 4, bcol = (t & 15) << 2;

    float4 rav, rbv;
    rav = *(const float4*)(Ab + (size_t)arow * lda + acol);
    rbv = *(const float4*)(Bb + (size_t)brow * N + bcol);
    As[0][acol+0][arow]=rav.x; As[0][acol+1][arow]=rav.y;
    As[0][acol+2][arow]=rav.z; As[0][acol+3][arow]=rav.w;
    *(float4*)&Bs[0][brow][bcol] = rbv;
    __syncthreads();

    int T = K >> 4;
    int cur = 0;
    for (int tt = 0; tt < T; tt++){
        if (tt + 1 < T){
            int k0 = (tt + 1) << 4;
            rav = *(const float4*)(Ab + (size_t)arow * lda + k0 + acol);
            rbv = *(const float4*)(Bb + (size_t)(k0 + brow) * N + bcol);
        }
#pragma unroll
        for (int kk = 0; kk < 16; kk++){
            float4 a4 = *(const float4*)&As[cur][kk][ty << 2];
            float4 b4 = *(const float4*)&Bs[cur][kk][tx << 2];
            float ar[4] = {a4.x, a4.y, a4.z, a4.w};
            float br[4] = {b4.x, b4.y, b4.z, b4.w};
#pragma unroll
            for (int ii = 0; ii < 4; ii++)
#pragma unroll
                for (int jj = 0; jj < 4; jj++)
                    acc[ii][jj] = fmaf(ar[ii], br[jj], acc[ii][jj]);
        }
        if (tt + 1 < T){
            int nxt = cur ^ 1;
            As[nxt][acol+0][arow]=rav.x; As[nxt][acol+1][arow]=rav.y;
            As[nxt][acol+2][arow]=rav.z; As[nxt][acol+3][arow]=rav.w;
            *(float4*)&Bs[nxt][brow][bcol] = rbv;
        }
        __syncthreads();
        cur ^= 1;
    }

    bool dokv = (KVH != nullptr) && (n0 >= 512);
#pragma unroll
    for (int ii = 0; ii < 4; ii++){
        int m = m0 + (ty << 2) + ii;
        int nn = n0 + (tx << 2);
        float v0 = acc[ii][0], v1 = acc[ii][1], v2 = acc[ii][2], v3 = acc[ii][3];
        if (bz){ v0 += bz[nn]; v1 += bz[nn+1]; v2 += bz[nn+2]; v3 += bz[nn+3]; }
        *(float4*)&Cb[(size_t)m * N + nn] = make_float4(v0, v1, v2, v3);
        if (dokv){
            __half2 h0 = __floats2half2_rn(v0, v1);
            __half2 h1 = __floats2half2_rn(v2, v3);
            __half2* hp = (__half2*)(KVH + (size_t)m * 1024 + (nn - 512));
            hp[0] = h0; hp[1] = h1;
        }
    }
}

// ============================================================
// split-K combine: out = P[0] + P[1] + bias  (4096x256 fp32)
// ============================================================
__global__ void __launch_bounds__(256) splitk_add(
    const float* __restrict__ P, const float* __restrict__ bias,
    float* __restrict__ out)
{
    int idx = blockIdx.x * 256 + threadIdx.x;          // float4 index
    float4 a = ((const float4*)P)[idx];
    float4 b = ((const float4*)(P + (size_t)NROWS * 256))[idx];
    float4 bb = ((const float4*)bias)[idx & 63];
    ((float4*)out)[idx] = make_float4(a.x+b.x+bb.x, a.y+b.y+bb.y,
                                      a.z+b.z+bb.z, a.w+b.w+bb.w);
}

// ============================================================
// Top-64 nearest neighbors per row: 3-pass radix select on
// fp32 distance bit patterns (non-negative -> order-preserving)
// ============================================================
__global__ void __launch_bounds__(256) topk_kernel(const float* __restrict__ coors)
{
    __shared__ int hist[2048];
    __shared__ int wsum[8];
    __shared__ int sel_bin, sel_base;
    __shared__ int res_cnt, eq_cnt;
    __shared__ int res[64];
    __shared__ int eqlist[128];

    int tid = threadIdx.x;
    int row = blockIdx.x;
    int b = row >> 11, i = row & 2047;
    const float* cbp = coors + (size_t)b * 2048 * 3;
    float xi = cbp[i*3+0], yi = cbp[i*3+1], zi = cbp[i*3+2];

    unsigned u[8];
#pragma unroll
    for (int r = 0; r < 8; r++){
        int c = r * 256 + tid;
        float dx = xi - cbp[c*3+0];
        float dy = yi - cbp[c*3+1];
        float dz = zi - cbp[c*3+2];
        u[r] = __float_as_uint(sqrtf(dx*dx + dy*dy + dz*dz));
    }

    int k = 64;
    unsigned prefix = 0, pmask = 0;
#pragma unroll
    for (int p = 0; p < 3; p++){
        const int sh = (p == 0) ? 21 : (p == 1) ? 10 : 0;
        const int nbins = (p == 2) ? 1024 : 2048;
        const unsigned bm = (unsigned)nbins - 1u;
        for (int x = tid; x < nbins; x += 256) hist[x] = 0;
        __syncthreads();
#pragma unroll
        for (int r = 0; r < 8; r++)
            if ((u[r] & pmask) == prefix) atomicAdd(&hist[(u[r] >> sh) & bm], 1);
        __syncthreads();
        int per = nbins >> 8;
        int s = 0;
        for (int q = 0; q < per; q++) s += hist[tid * per + q];
        int lane = tid & 31, wid = tid >> 5;
        int x = s;
#pragma unroll
        for (int o = 1; o < 32; o <<= 1){
            int y = __shfl_up_sync(0xffffffffu, x, o);
            if (lane >= o) x += y;
        }
        if (lane == 31) wsum[wid] = x;
        __syncthreads();
        int add = 0;
#pragma unroll
        for (int q = 0; q < 8; q++) if (q < wid) add += wsum[q];
        int incl = x + add;
        int excl = incl - s;
        if (excl < k && k <= incl){
            int running = excl;
            for (int q = 0; q < per; q++){
                int c = hist[tid * per + q];
                if (running < k && k <= running + c){
                    sel_bin = tid * per + q;
                    sel_base = running;
                    break;
                }
                running += c;
            }
        }
        __syncthreads();
        k -= sel_base;
        prefix |= ((unsigned)sel_bin) << sh;
        pmask |= bm << sh;
        __syncthreads();
    }
    unsigned D = prefix;
    if (tid == 0){ res_cnt = 0; eq_cnt = 0; }
    __syncthreads();
#pragma unroll
    for (int r = 0; r < 8; r++){
        int c = r * 256 + tid;
        if (u[r] < D){
            int p = atomicAdd(&res_cnt, 1);
            res[p] = c;
        } else if (u[r] == D){
            int p = atomicAdd(&eq_cnt, 1);
            if (p < 128) eqlist[p] = c;
        }
    }
    __syncthreads();
    if (tid == 0){
        int ec = eq_cnt < 128 ? eq_cnt : 128;
        int base = res_cnt;
        for (int a = 0; a < k; a++){      // take k smallest indices among ties
            int best = 0x7fffffff, bi = -1;
            for (int q = 0; q < ec; q++)
                if (eqlist[q] < best){ best = eqlist[q]; bi = q; }
            res[base + a] = best;
            if (bi >= 0) eqlist[bi] = 0x7fffffff;
        }
    }
    __syncthreads();
    if (tid < 64) g_nb[row * 64 + tid] = res[tid];
}

// ============================================================
// Fused per-row attention kernel: one block per (b,i)
// ============================================================
__global__ void __launch_bounds__(256, 5) main_kernel(
    const float* __restrict__ coors,
    const float* __restrict__ edges,
    const float* __restrict__ W_e1, const float* __restrict__ b_e1,
    const float* __restrict__ W_e2, const float* __restrict__ b_e2,
    const float* __restrict__ W_c,  const float* __restrict__ b_c,
    const float* __restrict__ W_g,  const float* __restrict__ b_g,
    const float* __restrict__ combine, const float* __restrict__ cscale,
    float* __restrict__ out_coors)
{
    __shared__ float q_s[512];
    __shared__ __half2 cs_h[2048];        // (cos,sin) per (j, pair)
    __shared__ float u_qk_attn[64*9];     // qkraw (phase<=MLP), attn (phase>=softmax)
    __shared__ float u_e_gs[64*17];       // edges (phase<=MLP), gelu(s) (phase>MLP)
    __shared__ float s_s[64][9];
    __shared__ float ws_s[64][9];
    __shared__ float gate_s[64][9];
    __shared__ float reln[64][4];
    __shared__ float t_s[64];
    __shared__ int   nb_s[64];
    __shared__ float we1[24*48];
    __shared__ float be1[48];
    __shared__ float we2[48*8];
    __shared__ float be2[8];
    __shared__ float wc[64], bc[8], wg[64], bg[8];
    __shared__ float delta_sm[3];

#define QKRAW(j,h)  u_qk_attn[(j)*9 + (h)]
#define ATTN(j,h)   u_qk_attn[(j)*9 + (h)]
#define ES(j,p)     u_e_gs[(j)*17 + (p)]
#define GS(j,h)     u_e_gs[(j)*17 + (h)]

    int tid = threadIdx.x;
    int w = tid >> 5, l = tid & 31;
    int dq = l & 7, jg = l >> 3;
    int row = blockIdx.x;
    int b = row >> 11, i = row & 2047;
    const __half* kvb = g_kvh + (size_t)b * 2048 * 1024;

    for (int x = tid; x < 1152; x += 256) we1[x] = W_e1[x];
    for (int x = tid; x < 384;  x += 256) we2[x] = W_e2[x];
    if (tid < 48) be1[tid] = b_e1[tid];
    if (tid < 8){ be2[tid] = b_e2[tid]; bc[tid] = b_c[tid]; bg[tid] = b_g[tid]; }
    if (tid < 64){ wc[tid] = W_c[tid]; wg[tid] = W_g[tid]; }
    if (tid < 3) delta_sm[tid] = 0.f;
    {
        const float* qrow = g_qkv + (size_t)row * 1536;
        for (int x = tid; x < 512; x += 256) q_s[x] = qrow[x];
    }
    if (tid < 64) nb_s[tid] = g_nb[row * 64 + tid];
    __syncthreads();

    float scl = cscale[0];
    if (tid < 64){
        int j = nb_s[tid];
        const float* cp = coors + (size_t)b * 2048 * 3;
        float dx = cp[i*3+0] - cp[j*3+0];
        float dy = cp[i*3+1] - cp[j*3+1];
        float dz = cp[i*3+2] - cp[j*3+2];
        float d = sqrtf(dx*dx + dy*dy + dz*dz);
        t_s[tid] = fminf(d * 100.f, 5000.f);
        float inv = scl / fmaxf(d, 1e-8f);
        reln[tid][0] = dx * inv;
        reln[tid][1] = dy * inv;
        reln[tid][2] = dz * inv;
    }
    __syncthreads();

    // rotary (cos,sin) table: 64 neighbors x 32 pairs, half2 packed
    const float NEG_L2T_OVER32 = -0.41524101186092029f;  // -log2(10000)/32
    for (int x = tid; x < 2048; x += 256){
        int j = x >> 5, li = x & 31;
        float invf = exp2f((float)li * NEG_L2T_OVER32);
        float ang = t_s[j] * invf;
        // Cody-Waite 2-term 2*pi range reduction (angles up to 5000 rad)
        float nq = rintf(ang * 0.15915494309189535f);
        float r = fmaf(nq, -6.2831854820251465f, ang);
        r = fmaf(nq, 1.7484556e-7f, r);
        float sv, cv;
        __sincosf(r, &sv, &cv);
        cs_h[x] = __floats2half2_rn(cv, sv);
    }

    // gather edges: 4 threads per neighbor, float4 global -> scalar smem
    {
        int j = tid >> 2, q4 = (tid & 3) << 2;
        const float* ep = edges + (((size_t)(b * 2048 + i)) * 2048 + (size_t)nb_s[j]) * 16 + q4;
        float4 ev = *(const float4*)ep;
        ES(j, q4+0) = ev.x; ES(j, q4+1) = ev.y;
        ES(j, q4+2) = ev.z; ES(j, q4+3) = ev.w;
    }
    __syncthreads();

    // k-pass: warp w = head w; lane (jg,dq): j = 4t+jg, dims dq*8..dq*8+7
    {
        float qreg[8];
#pragma unroll
        for (int x = 0; x < 8; x++) qreg[x] = q_s[w*64 + dq*8 + x];
#pragma unroll 4
        for (int t = 0; t < 16; t++){
            int j = t*4 + jg;
            const __half* kp = kvb + (size_t)nb_s[j] * 1024 + w*64 + dq*8;
            float4 kraw = *(const float4*)kp;
            const __half2* kh = (const __half2*)&kraw;
            float4 craw = *(const float4*)&cs_h[j*32 + dq*4];
            const __half2* ch = (const __half2*)&craw;
            float p = 0.f;
#pragma unroll
            for (int q = 0; q < 4; q++){
                float2 kv = __half22float2(kh[q]);
                float2 cs = __half22float2(ch[q]);
                float kr0 = kv.x*cs.x - kv.y*cs.y;
                float kr1 = fmaf(kv.y, cs.x, kv.x*cs.y);
                p = fmaf(qreg[2*q], kr0, p);
                p = fmaf(qreg[2*q+1], kr1, p);
            }
            p += __shfl_xor_sync(0xffffffffu, p, 1);
            p += __shfl_xor_sync(0xffffffffu, p, 2);
            p += __shfl_xor_sync(0xffffffffu, p, 4);
            if (dq == 0) QKRAW(j, w) = p;
        }
    }
    for (int x = tid; x < 512; x += 256) s_s[x >> 3][x & 7] = be2[x & 7];
    __syncthreads();

    // edge MLP 24 -> 48 (GELU) -> 8, fused: 4 threads/neighbor, 12 hidden each
    {
        int j = tid & 63, part = tid >> 6, hd0 = part * 12;
        float hid[12];
#pragma unroll
        for (int hh = 0; hh < 12; hh++){
            int hd = hd0 + hh;
            float z = be1[hd];
#pragma unroll
            for (int p = 0; p < 8; p++)  z = fmaf(QKRAW(j, p), we1[p*48 + hd], z);
#pragma unroll
            for (int p = 0; p < 16; p++) z = fmaf(ES(j, p), we1[(8+p)*48 + hd], z);
            hid[hh] = gelu_exact(z);
        }
#pragma unroll
        for (int h = 0; h < 8; h++){
            float acc = 0.f;
#pragma unroll
            for (int hh = 0; hh < 12; hh++)
                acc = fmaf(hid[hh], we2[(hd0+hh)*8 + h], acc);
            atomicAdd(&s_s[j][h], acc);
        }
    }
    __syncthreads();

    for (int x = tid; x < 512; x += 256){
        int jj = x >> 3, h = x & 7;
        GS(jj, h) = gelu_exact(s_s[jj][h]);
    }
    __syncthreads();
    for (int x = tid; x < 512; x += 256){
        int jj = x >> 3, h = x & 7;
        float cw = bc[h], gt = bg[h];
#pragma unroll
        for (int p = 0; p < 8; p++){
            cw = fmaf(GS(jj, p), wc[p*8 + h], cw);
            gt = fmaf(s_s[jj][p], wg[p*8 + h], gt);
        }
        ws_s[jj][h] = cw;              // coor logits (pre-softmax)
        gate_s[jj][h] = tanhf(gt);
    }
    __syncthreads();

    // dual softmax over j per head (warp w); lanes cover j = l and l+32
    {
        float sa = s_s[l][w], sb = s_s[l+32][w];
        float m = fmaxf(sa, sb);
#pragma unroll
        for (int o = 16; o > 0; o >>= 1) m = fmaxf(m, __shfl_xor_sync(0xffffffffu, m, o));
        float ea = __expf(sa - m), eb = __expf(sb - m);
        float sum = ea + eb;
#pragma unroll
        for (int o = 16; o > 0; o >>= 1) sum += __shfl_xor_sync(0xffffffffu, sum, o);
        float inv = 1.f / sum;
        float at_a = ea * inv, at_b = eb * inv;

        float ca = ws_s[l][w], cb2 = ws_s[l+32][w];
        float m2 = fmaxf(ca, cb2);
#pragma unroll
        for (int o = 16; o > 0; o >>= 1) m2 = fmaxf(m2, __shfl_xor_sync(0xffffffffu, m2, o));
        float e2a = __expf(ca - m2), e2b = __expf(cb2 - m2);
        float sum2 = e2a + e2b;
#pragma unroll
        for (int o = 16; o > 0; o >>= 1) sum2 += __shfl_xor_sync(0xffffffffu, sum2, o);
        float inv2 = 1.f / sum2;
        __syncthreads();               // qkraw fully consumed before attn overwrite
        ATTN(l, w)    = at_a;
        ATTN(l+32, w) = at_b;
        ws_s[l][w]    = e2a * inv2 * gate_s[l][w];
        ws_s[l+32][w] = e2b * inv2 * gate_s[l+32][w];
    }
    __syncthreads();

    // coordinate delta: warp w accumulates its head, combine across heads
    {
        float wa = ws_s[l][w], wb = ws_s[l+32][w];
        float d0 = wa * reln[l][0] + wb * reln[l+32][0];
        float d1 = wa * reln[l][1] + wb * reln[l+32][1];
        float d2 = wa * reln[l][2] + wb * reln[l+32][2];
#pragma unroll
        for (int o = 16; o > 0; o >>= 1){
            d0 += __shfl_xor_sync(0xffffffffu, d0, o);
            d1 += __shfl_xor_sync(0xffffffffu, d1, o);
            d2 += __shfl_xor_sync(0xffffffffu, d2, o);
        }
        if (l == 0){
            float cmb = combine[w];
            atomicAdd(&delta_sm[0], d0 * cmb);
            atomicAdd(&delta_sm[1], d1 * cmb);
            atomicAdd(&delta_sm[2], d2 * cmb);
        }
    }

    // v-pass: attn-weighted rotated v accumulation, same lane tiling
    {
        float acc[8];
#pragma unroll
        for (int x = 0; x < 8; x++) acc[x] = 0.f;
#pragma unroll 4
        for (int t = 0; t < 16; t++){
            int j = t*4 + jg;
            float a = ATTN(j, w);
            const __half* vp = kvb + (size_t)nb_s[j] * 1024 + 512 + w*64 + dq*8;
            float4 vraw = *(const float4*)vp;
            const __half2* vh = (const __half2*)&vraw;
            float4 craw = *(const float4*)&cs_h[j*32 + dq*4];
            const __half2* ch = (const __half2*)&craw;
#pragma unroll
            for (int q = 0; q < 4; q++){
                float2 vv = __half22float2(vh[q]);
                float2 cs = __half22float2(ch[q]);
                acc[2*q]   = fmaf(a, vv.x*cs.x - vv.y*cs.y, acc[2*q]);
                acc[2*q+1] = fmaf(a, fmaf(vv.y, cs.x, vv.x*cs.y), acc[2*q+1]);
            }
        }
#pragma unroll
        for (int x = 0; x < 8; x++){
            acc[x] += __shfl_xor_sync(0xffffffffu, acc[x], 8);
            acc[x] += __shfl_xor_sync(0xffffffffu, acc[x], 16);
        }
        if (jg == 0){
            float4* po = (float4*)&g_att[(size_t)row * 512 + w*64 + dq*8];
            po[0] = make_float4(acc[0], acc[1], acc[2], acc[3]);
            po[1] = make_float4(acc[4], acc[5], acc[6], acc[7]);
        }
    }
    __syncthreads();
    if (tid < 3) out_coors[row * 3 + tid] = delta_sm[tid];
}

// ============================================================
extern "C" void kernel_launch(void* const* d_in, const int* in_sizes, int n_in,
                              void* d_out, int out_size)
{
    const float* feats   = (const float*)d_in[0];
    const float* coors   = (const float*)d_in[1];
    const float* edges   = (const float*)d_in[2];
    const float* W_qkv   = (const float*)d_in[3];
    const float* W_out   = (const float*)d_in[4];
    const float* b_out   = (const float*)d_in[5];
    const float* W_e1    = (const float*)d_in[6];
    const float* b_e1    = (const float*)d_in[7];
    const float* W_e2    = (const float*)d_in[8];
    const float* b_e2    = (const float*)d_in[9];
    const float* W_c     = (const float*)d_in[10];
    const float* b_c     = (const float*)d_in[11];
    const float* W_g     = (const float*)d_in[12];
    const float* b_g     = (const float*)d_in[13];
    const float* combine = (const float*)d_in[14];
    const float* cscale  = (const float*)d_in[15];
    float* out = (float*)d_out;

    void *p_qkv = 0, *p_att = 0, *p_kvh = 0;
    cudaGetSymbolAddress(&p_qkv, g_qkv);
    cudaGetSymbolAddress(&p_att, g_att);
    cudaGetSymbolAddress(&p_kvh, g_kvh);

    // 1) QKV projection: (4096,256)@(256,1536); epilogue packs fp16 k|v
    sgemm_db<<<dim3(1536/64, 4096/64, 1), 256>>>(
        feats, W_qkv, nullptr, (float*)p_qkv, (__half*)p_kvh,
        4096, 1536, 256, 256);

    // 2) top-64 neighbors per row
    topk_kernel<<<4096, 256>>>(coors);

    // 3) fused attention; writes g_att and coors_delta region of d_out
    main_kernel<<<4096, 256>>>(coors, edges,
        W_e1, b_e1, W_e2, b_e2, W_c, b_c, W_g, b_g,
        combine, cscale, out + 2*2048*256);

    // 4) output projection, split-K=2: partials into g_qkv scratch, then add+bias
    sgemm_db<<<dim3(256/64, 4096/64, 2), 256>>>(
        (const float*)p_att, W_out, nullptr, (float*)p_qkv, nullptr,
        4096, 256, 256, 512);
    splitk_add<<<1024, 256>>>((const float*)p_qkv, b_out, out);
}